// round 8
// baseline (speedup 1.0000x reference)
#include <cuda_runtime.h>
#include <cuda_fp16.h>
#include <cstdint>

#define N_NODES 4096
#define FEAT    32
#define G3      192
#define HDIM    64
#define BATCH   4
#define TSTEPS  8
#define NBT     (BATCH*TSTEPS)           // 32
#define MAXD    128
#define NROWS   (NBT*N_NODES)            // 131072

// ---- gru mma kernel geometry ----
#define NP      64                        // nodes per block
#define GT      256                       // threads (8 warps = 4 m16 x 2 hd-halves)

// smem float offsets
#define O_B     0                         // B frags [6 k16][24 tiles][32 lanes][bh0 bh1 bl0 bl1]
#define O_AH    18432                     // A hi frags [6 k16][4 m16][32 lanes][4]
#define O_AL    21504                     // A lo frags
#define O_BIAS  24576                     // [256] r|z|ni|nh
#define O_WD    24832                     // [64]
#define O_HEAD  24896                     // [128]
#define SM_FLOATS 25024                   // 100096 bytes

// -------- static device scratch --------
__device__ int   g_row_len[N_NODES];
__device__ float g_row_wsum[N_NODES];
__device__ int2  g_ell_cv[N_NODES * MAXD];
__device__ float g_bnA[FEAT];
__device__ float g_bnC[FEAT];
__device__ float g_Wcomb[FEAT * G3];
__device__ float g_bcomb[G3];
__device__ float g_partN[N_NODES * 64];
__device__ float g_xT[(size_t)N_NODES * NBT * FEAT];
__device__ float g_ya[(size_t)NROWS * FEAT];

// ============================================================
// helpers
// ============================================================
__device__ __forceinline__ float sigm(float v) { return __fdividef(1.0f, 1.0f + __expf(-v)); }
__device__ __forceinline__ float tanh_fast(float v) {
    const float e = __expf(-2.0f * v);
    return __fdividef(1.0f - e, 1.0f + e);
}
// pack two floats to f16x2 (first arg -> low half)
__device__ __forceinline__ uint32_t pack_f16x2(float lo_val, float hi_val) {
    uint32_t r;
    asm("cvt.rn.f16x2.f32 %0, %1, %2;" : "=r"(r) : "f"(hi_val), "f"(lo_val));
    return r;
}
__device__ __forceinline__ void mma16(float* d, const uint4& a, const uint2& b) {
    asm volatile(
        "mma.sync.aligned.m16n8k16.row.col.f32.f16.f16.f32 "
        "{%0,%1,%2,%3}, {%4,%5,%6,%7}, {%8,%9}, {%0,%1,%2,%3};"
        : "+f"(d[0]), "+f"(d[1]), "+f"(d[2]), "+f"(d[3])
        : "r"(a.x), "r"(a.y), "r"(a.z), "r"(a.w), "r"(b.x), "r"(b.y));
}

// ============================================================
// Kernel 1: dense adj -> packed ELL (deterministic ballot order)
// MLP=8: preload 8 chunks per warp before the ballot chain.
// ============================================================
__global__ void build_ell_kernel(const float* __restrict__ adj)
{
    const int warp = (blockIdx.x * blockDim.x + threadIdx.x) >> 5;
    const int lane = threadIdx.x & 31;
    const float* row = adj + (size_t)warp * N_NODES;
    const int base = warp * MAXD;
    int cnt = 0; float wsum = 0.f;
    #pragma unroll 1
    for (int g = 0; g < N_NODES / 256; ++g) {
        float v[8];
        #pragma unroll
        for (int j = 0; j < 8; ++j) v[j] = row[g * 256 + j * 32 + lane];
        #pragma unroll
        for (int j = 0; j < 8; ++j) {
            const int c = g * 256 + j * 32 + lane;
            wsum += v[j];
            const unsigned mask = __ballot_sync(0xffffffffu, v[j] != 0.0f);
            if (v[j] != 0.0f) {
                const int pos = cnt + __popc(mask & ((1u << lane) - 1u));
                if (pos < MAXD) g_ell_cv[base + pos] = make_int2(c, __float_as_int(v[j]));
            }
            cnt += __popc(mask);
        }
    }
    #pragma unroll
    for (int o = 16; o > 0; o >>= 1) wsum += __shfl_xor_sync(0xffffffffu, wsum, o);
    if (lane == 0) {
        g_row_len[warp]  = cnt < MAXD ? cnt : MAXD;
        g_row_wsum[warp] = wsum;
    }
}

// ============================================================
// Kernel 2: transpose x + per-node BN partials
// ============================================================
__global__ void __launch_bounds__(256)
transpose_bn_kernel(const float* __restrict__ x)
{
    const int n   = blockIdx.x;
    const int tid = threadIdx.x;
    const int bt  = tid >> 3;
    const int f0  = (tid & 7) * 4;
    const int lane = tid & 31;
    const int w    = tid >> 5;

    const float4 v = *(const float4*)(x + ((size_t)bt * N_NODES + n) * FEAT + f0);
    *(float4*)(g_xT + (size_t)n * (NBT * FEAT) + bt * FEAT + f0) = v;

    float s0 = v.x, s1 = v.y, s2 = v.z, s3 = v.w;
    float q0 = v.x * v.x, q1 = v.y * v.y, q2 = v.z * v.z, q3 = v.w * v.w;
    #pragma unroll
    for (int o = 8; o <= 16; o <<= 1) {
        s0 += __shfl_xor_sync(0xffffffffu, s0, o);
        s1 += __shfl_xor_sync(0xffffffffu, s1, o);
        s2 += __shfl_xor_sync(0xffffffffu, s2, o);
        s3 += __shfl_xor_sync(0xffffffffu, s3, o);
        q0 += __shfl_xor_sync(0xffffffffu, q0, o);
        q1 += __shfl_xor_sync(0xffffffffu, q1, o);
        q2 += __shfl_xor_sync(0xffffffffu, q2, o);
        q3 += __shfl_xor_sync(0xffffffffu, q3, o);
    }
    __shared__ float sh[8][64];
    if (lane < 8) {
        sh[w][f0 + 0]      = s0;  sh[w][f0 + 1]      = s1;
        sh[w][f0 + 2]      = s2;  sh[w][f0 + 3]      = s3;
        sh[w][32 + f0 + 0] = q0;  sh[w][32 + f0 + 1] = q1;
        sh[w][32 + f0 + 2] = q2;  sh[w][32 + f0 + 3] = q3;
    }
    __syncthreads();
    if (tid < 64) {
        float a = 0.f;
        #pragma unroll
        for (int i = 0; i < 8; ++i) a += sh[i][tid];
        g_partN[n * 64 + tid] = a;
    }
}

// ============================================================
// Kernel 3: finalize BN affine + Wcomb/bcomb
// ============================================================
__global__ void __launch_bounds__(256)
finalize_kernel(const float* __restrict__ gamma,
                const float* __restrict__ beta,
                const float* __restrict__ Wgcn,
                const float* __restrict__ bgcn,
                const float* __restrict__ Wih,
                const float* __restrict__ bih)
{
    __shared__ float red[4][64];
    __shared__ float s_sum[32], s_sq[32];
    const int tid = threadIdx.x;
    {
        float a = 0.f;
        const int c = tid & 63;
        for (int n = tid >> 6; n < N_NODES; n += 4) a += g_partN[n * 64 + c];
        red[tid >> 6][c] = a;
    }
    __syncthreads();
    if (tid < 64) {
        const float a = red[0][tid] + red[1][tid] + red[2][tid] + red[3][tid];
        if (tid < 32) s_sum[tid] = a; else s_sq[tid - 32] = a;
    }
    __syncthreads();
    if (tid < 32) {
        const float M    = (float)NROWS;
        const float mean = s_sum[tid] / M;
        const float var  = s_sq[tid] / M - mean * mean;
        const float aK   = gamma[tid] * (1.0f / sqrtf(var + 1e-5f));
        g_bnA[tid] = aK;
        g_bnC[tid] = beta[tid] - mean * aK;
    }
    for (int idx = tid; idx < FEAT * G3; idx += blockDim.x) {
        const int f = idx / G3, j = idx % G3;
        float acc = 0.f;
        #pragma unroll 8
        for (int c = 0; c < 32; ++c) acc += Wgcn[f * 32 + c] * Wih[c * G3 + j];
        g_Wcomb[idx] = acc;
    }
    if (tid < G3) {
        float acc = bih[tid];
        #pragma unroll 8
        for (int c = 0; c < 32; ++c) acc += bgcn[c] * Wih[c * G3 + tid];
        g_bcomb[tid] = acc;
    }
}

// ============================================================
// Kernel 4: aggregation (one block = one node, all 32 bt)
// unroll 4 neighbors -> 16 loads in flight
// ============================================================
__global__ void __launch_bounds__(256)
agg_kernel()
{
    const int m   = blockIdx.x;
    const int tid = threadIdx.x;
    const int f   = tid & 31;
    const int bt0 = tid >> 5;

    const int len = g_row_len[m];
    const float wsum = g_row_wsum[m];
    const int2* cv = g_ell_cv + m * MAXD;

    float a0 = 0.f, a1 = 0.f, a2 = 0.f, a3 = 0.f;
    const int off = bt0 * FEAT + f;

    int k = 0;
    for (; k + 3 < len; k += 4) {
        const int2 e0 = cv[k], e1 = cv[k + 1], e2 = cv[k + 2], e3 = cv[k + 3];
        const float w0 = __int_as_float(e0.y), w1 = __int_as_float(e1.y);
        const float w2 = __int_as_float(e2.y), w3 = __int_as_float(e3.y);
        const float* p0 = g_xT + (size_t)e0.x * (NBT * FEAT) + off;
        const float* p1 = g_xT + (size_t)e1.x * (NBT * FEAT) + off;
        const float* p2 = g_xT + (size_t)e2.x * (NBT * FEAT) + off;
        const float* p3 = g_xT + (size_t)e3.x * (NBT * FEAT) + off;
        const float v00 = p0[0], v01 = p0[256], v02 = p0[512], v03 = p0[768];
        const float v10 = p1[0], v11 = p1[256], v12 = p1[512], v13 = p1[768];
        const float v20 = p2[0], v21 = p2[256], v22 = p2[512], v23 = p2[768];
        const float v30 = p3[0], v31 = p3[256], v32 = p3[512], v33 = p3[768];
        a0 += w0 * v00; a1 += w0 * v01; a2 += w0 * v02; a3 += w0 * v03;
        a0 += w1 * v10; a1 += w1 * v11; a2 += w1 * v12; a3 += w1 * v13;
        a0 += w2 * v20; a1 += w2 * v21; a2 += w2 * v22; a3 += w2 * v23;
        a0 += w3 * v30; a1 += w3 * v31; a2 += w3 * v32; a3 += w3 * v33;
    }
    for (; k < len; ++k) {
        const int2 e = cv[k];
        const float w = __int_as_float(e.y);
        const float* p = g_xT + (size_t)e.x * (NBT * FEAT) + off;
        a0 += w * p[0]; a1 += w * p[256]; a2 += w * p[512]; a3 += w * p[768];
    }

    const float A = g_bnA[f];
    const float C = g_bnC[f] * wsum;
    g_ya[((size_t)(bt0 +  0) * N_NODES + m) * FEAT + f] = A * a0 + C;
    g_ya[((size_t)(bt0 +  8) * N_NODES + m) * FEAT + f] = A * a1 + C;
    g_ya[((size_t)(bt0 + 16) * N_NODES + m) * FEAT + f] = A * a2 + C;
    g_ya[((size_t)(bt0 + 24) * N_NODES + m) * FEAT + f] = A * a3 + C;
}

// ============================================================
// Kernel 5: GRU scan via mma.sync m16n8k16 fp16 (3-term split).
// block = 64 nodes x 1 batch, 256 threads, 2 blocks/SM, grid 256.
// 2 syncs per timestep: [GEMM] sync [epilogue + stage ya_{t+1}] sync [out]
// ============================================================
#define GK16(C, ACCN)                                                            \
{                                                                                \
    const uint4 ah = *(const uint4*)&sAh[(((C) * 4 + mw) * 32 + lane) * 4];      \
    const uint4 al = *(const uint4*)&sAl[(((C) * 4 + mw) * 32 + lane) * 4];      \
    _Pragma("unroll")                                                            \
    for (int tt = 0; tt < 12; ++tt) {                                            \
        const uint4 bq = *(const uint4*)&sB[(((C) * 24 + Ht + tt) * 32 + lane) * 4]; \
        const uint2 bh = make_uint2(bq.x, bq.y);                                 \
        const uint2 bl = make_uint2(bq.z, bq.w);                                 \
        float* cp = (tt < 8) ? accRZ[tt] : ACCN[tt - 8];                         \
        mma16(cp, ah, bh);                                                       \
        mma16(cp, al, bh);                                                       \
        mma16(cp, ah, bl);                                                       \
    }                                                                            \
}

__global__ void __launch_bounds__(GT, 2)
gru_mma_kernel(const float* __restrict__ Whh,
               const float* __restrict__ bhh,
               const float* __restrict__ Wd,
               const float* __restrict__ bd,
               float* __restrict__ out)
{
    extern __shared__ float sm[];
    float* sB    = sm + O_B;
    float* sAh   = sm + O_AH;
    float* sAl   = sm + O_AL;
    float* sBias = sm + O_BIAS;
    float* sWd   = sm + O_WD;
    float* sHead = sm + O_HEAD;

    const int tid  = threadIdx.x;
    const int wid  = tid >> 5;
    const int lane = tid & 31;
    const int mw   = wid >> 1;          // m16 tile 0..3
    const int H    = wid & 1;           // hd half
    const int Ht   = H * 12;            // B tile base

    const int b   = blockIdx.x >> 6;
    const int gm0 = (blockIdx.x & 63) * NP;

    // ---- zero A fragment regions (h0 = 0) ----
    for (int i = tid; i < 3072; i += GT) { sAh[i] = 0.0f; sAl[i] = 0.0f; }

    // ---- stage B fragments (fp16 hi/lo, permuted cols) ----
    {
        __half* pB = (__half*)sB;
        for (int idx = tid; idx < 96 * G3; idx += GT) {
            const int k = idx / G3, n = idx % G3;
            const float w = (k < 32) ? g_Wcomb[k * G3 + n] : Whh[(k - 32) * G3 + n];
            const __half hh = __float2half_rn(w);
            const __half hl = __float2half_rn(w - __half2float(hh));
            const int g    = n >> 6;
            const int hd   = n & 63;
            const int Hh   = hd >> 5;
            const int hdl  = hd & 31;
            const int tile = Hh * 12 + g * 4 + (hdl >> 3);
            const int ccol = hdl & 7;
            const int chunk = k >> 4;
            const int rem   = k & 15;
            const int lt    = ccol * 4 + ((rem & 7) >> 1);
            const int regB  = (rem >= 8) ? 1 : 0;
            const int hb    = rem & 1;
            const int base  = ((chunk * 24 + tile) * 32 + lt) * 4;
            pB[(base + regB) * 2 + hb]     = hh;
            pB[(base + 2 + regB) * 2 + hb] = hl;
        }
    }
    if (tid < HDIM) {
        sBias[tid]       = g_bcomb[tid]       + bhh[tid];        // r
        sBias[64 + tid]  = g_bcomb[64 + tid]  + bhh[64 + tid];   // z
        sBias[128 + tid] = g_bcomb[128 + tid];                   // n_i
        sBias[192 + tid] = bhh[128 + tid];                       // n_h
        sWd[tid]         = Wd[tid];
    }
    const float bdv = bd[0];

    // ---- epilogue geometry ----
    const int gr = lane >> 2;
    const int c0 = (lane & 3) * 2;

    float hprev[4][4];
    #pragma unroll
    for (int t = 0; t < 4; ++t)
        #pragma unroll
        for (int s = 0; s < 4; ++s) hprev[t][s] = 0.0f;

    // ---- ya staging geometry ----
    const int nodeS = tid >> 2;           // 0..63
    const int fc    = tid & 3;            // feature chunk: f base = fc*8
    const int baseS = (((fc >> 1) * 4 + (nodeS >> 4)) * 32 + (nodeS & 7) * 4) * 4
                      + ((fc & 1) ? 2 : 0) + (((nodeS & 15) >= 8) ? 1 : 0);

    // ---- stage ya_0 ----
    {
        const float* p = g_ya + ((size_t)(b * TSTEPS) * N_NODES + gm0 + nodeS) * FEAT + fc * 8;
        const float4 q0 = *(const float4*)(p);
        const float4 q1 = *(const float4*)(p + 4);
        float v[8];
        *(float4*)(v) = q0; *(float4*)(v + 4) = q1;
        #pragma unroll
        for (int j = 0; j < 4; ++j) {
            const float a = v[2 * j], bb = v[2 * j + 1];
            const __half ha = __float2half_rn(a);
            const __half hb = __float2half_rn(bb);
            sAh[baseS + j * 4] = __uint_as_float(pack_f16x2(a, bb));
            sAl[baseS + j * 4] = __uint_as_float(pack_f16x2(a - __half2float(ha),
                                                            bb - __half2float(hb)));
        }
    }
    __syncthreads();

    float4 pf0, pf1;

    for (int t8 = 0; t8 < TSTEPS; ++t8) {
        // ---- accumulators ----
        float accRZ[8][4], accNi[4][4], accNh[4][4];
        #pragma unroll
        for (int t = 0; t < 8; ++t)
            #pragma unroll
            for (int s = 0; s < 4; ++s) accRZ[t][s] = 0.0f;
        #pragma unroll
        for (int t = 0; t < 4; ++t)
            #pragma unroll
            for (int s = 0; s < 4; ++s) { accNi[t][s] = 0.0f; accNh[t][s] = 0.0f; }

        GK16(0, accNi) GK16(1, accNi)
        GK16(2, accNh) GK16(3, accNh) GK16(4, accNh) GK16(5, accNh)

        // prefetch next ya during GEMM
        if (t8 + 1 < TSTEPS) {
            const float* p = g_ya + ((size_t)(b * TSTEPS + t8 + 1) * N_NODES + gm0 + nodeS) * FEAT + fc * 8;
            pf0 = *(const float4*)(p);
            pf1 = *(const float4*)(p + 4);
        }
        __syncthreads();   // all warps done reading A frags (ya_t + h_t)

        // ---- register epilogue: gates, h update, head, h-frag + ya_{t+1} staging ----
        float hp0 = 0.0f, hp1 = 0.0f;
        #pragma unroll
        for (int t = 0; t < 4; ++t) {
            float hv[4];
            #pragma unroll
            for (int s = 0; s < 4; ++s) {
                const int cc = c0 + (s & 1);
                const int hd = H * 32 + t * 8 + cc;
                const float r = sigm(accRZ[t][s]     + sBias[hd]);
                const float z = sigm(accRZ[t + 4][s] + sBias[64 + hd]);
                const float n = tanh_fast(accNi[t][s] + sBias[128 + hd]
                                          + r * (accNh[t][s] + sBias[192 + hd]));
                hv[s] = (1.0f - z) * n + z * hprev[t][s];
                hprev[t][s] = hv[s];
            }
            hp0 += hv[0] * sWd[H * 32 + t * 8 + c0] + hv[1] * sWd[H * 32 + t * 8 + c0 + 1];
            hp1 += hv[2] * sWd[H * 32 + t * 8 + c0] + hv[3] * sWd[H * 32 + t * 8 + c0 + 1];
            // write h back into A fragments at k = 32 + H*32 + t*8 + cc
            const int chunk = 2 + H * 2 + (t >> 1);
            const int reg2  = (t & 1) * 2;
            const int base  = ((chunk * 4 + mw) * 32 + lane) * 4;
            const __half h0 = __float2half_rn(hv[0]);
            const __half h1 = __float2half_rn(hv[1]);
            const __half h2 = __float2half_rn(hv[2]);
            const __half h3 = __float2half_rn(hv[3]);
            sAh[base + reg2]     = __uint_as_float(pack_f16x2(hv[0], hv[1]));
            sAh[base + reg2 + 1] = __uint_as_float(pack_f16x2(hv[2], hv[3]));
            sAl[base + reg2]     = __uint_as_float(pack_f16x2(hv[0] - __half2float(h0),
                                                              hv[1] - __half2float(h1)));
            sAl[base + reg2 + 1] = __uint_as_float(pack_f16x2(hv[2] - __half2float(h2),
                                                              hv[3] - __half2float(h3)));
        }
        // stage ya_{t+1} (region disjoint from h frags)
        if (t8 + 1 < TSTEPS) {
            float v[8];
            *(float4*)(v) = pf0; *(float4*)(v + 4) = pf1;
            #pragma unroll
            for (int j = 0; j < 4; ++j) {
                const float a = v[2 * j], bb = v[2 * j + 1];
                const __half ha = __float2half_rn(a);
                const __half hb = __float2half_rn(bb);
                sAh[baseS + j * 4] = __uint_as_float(pack_f16x2(a, bb));
                sAl[baseS + j * 4] = __uint_as_float(pack_f16x2(a - __half2float(ha),
                                                                bb - __half2float(hb)));
            }
        }
        // head reduce across the 4 lanes sharing gr
        hp0 += __shfl_xor_sync(0xffffffffu, hp0, 1);
        hp0 += __shfl_xor_sync(0xffffffffu, hp0, 2);
        hp1 += __shfl_xor_sync(0xffffffffu, hp1, 1);
        hp1 += __shfl_xor_sync(0xffffffffu, hp1, 2);
        if ((lane & 3) == 0) {
            sHead[H * 64 + mw * 16 + gr]     = hp0;
            sHead[H * 64 + mw * 16 + gr + 8] = hp1;
        }
        __syncthreads();   // h frags + ya frags + sHead complete

        if (tid < NP) {
            out[(size_t)(b * TSTEPS + t8) * N_NODES + gm0 + tid] =
                bdv + sHead[tid] + sHead[64 + tid];
        }
        // out STG overlaps the next iteration's GEMM (no barrier between).
    }
}

// ============================================================
// launch
// ============================================================
extern "C" void kernel_launch(void* const* d_in, const int* in_sizes, int n_in,
                              void* d_out, int out_size)
{
    const float* x     = (const float*)d_in[0];
    const float* adj   = (const float*)d_in[1];
    const float* gamma = (const float*)d_in[2];
    const float* beta  = (const float*)d_in[3];
    const float* Wgcn  = (const float*)d_in[4];
    const float* bgcn  = (const float*)d_in[5];
    const float* Wih   = (const float*)d_in[6];
    const float* Whh   = (const float*)d_in[7];
    const float* bih   = (const float*)d_in[8];
    const float* bhh   = (const float*)d_in[9];
    const float* Wd    = (const float*)d_in[10];
    const float* bd    = (const float*)d_in[11];
    float* out = (float*)d_out;

    const int smem_bytes = SM_FLOATS * (int)sizeof(float);   // 100096
    cudaFuncSetAttribute(gru_mma_kernel, cudaFuncAttributeMaxDynamicSharedMemorySize, smem_bytes);

    build_ell_kernel<<<N_NODES / 8, 256>>>(adj);
    transpose_bn_kernel<<<N_NODES, 256>>>(x);
    finalize_kernel<<<1, 256>>>(gamma, beta, Wgcn, bgcn, Wih, bih);
    agg_kernel<<<N_NODES, 256>>>();
    gru_mma_kernel<<<BATCH * (N_NODES / NP), GT, smem_bytes>>>(Whh, bhh, Wd, bd, out);
}

// round 9
// speedup vs baseline: 1.4170x; 1.4170x over previous
#include <cuda_runtime.h>
#include <cuda_fp16.h>
#include <cstdint>

#define N_NODES 4096
#define FEAT    32
#define G3      192
#define HDIM    64
#define BATCH   4
#define TSTEPS  8
#define NBT     (BATCH*TSTEPS)           // 32
#define MAXD    128
#define NROWS   (NBT*N_NODES)            // 131072

// ---- gru mma kernel geometry ----
#define NP      64                        // nodes per block
#define GT      256                       // threads (8 warps = 4 m16 x 2 hd-halves)

// smem float offsets (gru)
#define O_B     0                         // B frags [6 k16][24 tiles][32 lanes][bh0 bh1 bl0 bl1]
#define O_AH    18432                     // A hi frags [6 k16][4 m16][32 lanes][4]
#define O_AL    21504                     // A lo frags
#define O_BIAS  24576                     // [256] r|z|ni|nh
#define O_WD    24832                     // [64]
#define O_HEAD  24896                     // [128]
#define SM_FLOATS 25024                   // 100096 bytes

// -------- static device scratch --------
__device__ int   g_row_len[N_NODES];
__device__ float g_row_wsum[N_NODES];
__device__ int2  g_ell_cv[N_NODES * MAXD];
__device__ float g_Wcomb[FEAT * G3];
__device__ float g_bcomb[G3];
__device__ float g_partN[64 * N_NODES];          // TRANSPOSED: [stat c][node n]
__device__ float g_stat[64];                     // 0-31 sum, 32-63 sumsq per feature
__device__ float g_xT[(size_t)N_NODES * NBT * FEAT];
__device__ float g_ya[(size_t)NROWS * FEAT];

// ============================================================
// helpers
// ============================================================
__device__ __forceinline__ float sigm(float v) { return __fdividef(1.0f, 1.0f + __expf(-v)); }
__device__ __forceinline__ float tanh_fast(float v) {
    const float e = __expf(-2.0f * v);
    return __fdividef(1.0f - e, 1.0f + e);
}
// pack two floats to f16x2 (first arg -> low half)
__device__ __forceinline__ uint32_t pack_f16x2(float lo_val, float hi_val) {
    uint32_t r;
    asm("cvt.rn.f16x2.f32 %0, %1, %2;" : "=r"(r) : "f"(hi_val), "f"(lo_val));
    return r;
}
__device__ __forceinline__ void mma16(float* d, const uint4& a, const uint2& b) {
    asm volatile(
        "mma.sync.aligned.m16n8k16.row.col.f32.f16.f16.f32 "
        "{%0,%1,%2,%3}, {%4,%5,%6,%7}, {%8,%9}, {%0,%1,%2,%3};"
        : "+f"(d[0]), "+f"(d[1]), "+f"(d[2]), "+f"(d[3])
        : "r"(a.x), "r"(a.y), "r"(a.z), "r"(a.w), "r"(b.x), "r"(b.y));
}

// ============================================================
// Kernel 1 (fused prep): blocks [0,512)   -> dense adj -> packed ELL
//                        blocks [512,4608)-> transpose x + BN partials
// ============================================================
__global__ void __launch_bounds__(256)
prep_kernel(const float* __restrict__ adj, const float* __restrict__ x)
{
    const int tid  = threadIdx.x;
    const int lane = tid & 31;
    const int w    = tid >> 5;

    if (blockIdx.x < 512) {
        // ---------- ELL build: warp = one adjacency row, MLP=8 ----------
        const int warp = blockIdx.x * 8 + w;
        const float* row = adj + (size_t)warp * N_NODES;
        const int base = warp * MAXD;
        int cnt = 0; float wsum = 0.f;
        #pragma unroll 1
        for (int g = 0; g < N_NODES / 256; ++g) {
            float v[8];
            #pragma unroll
            for (int j = 0; j < 8; ++j) v[j] = row[g * 256 + j * 32 + lane];
            #pragma unroll
            for (int j = 0; j < 8; ++j) {
                const int c = g * 256 + j * 32 + lane;
                wsum += v[j];
                const unsigned mask = __ballot_sync(0xffffffffu, v[j] != 0.0f);
                if (v[j] != 0.0f) {
                    const int pos = cnt + __popc(mask & ((1u << lane) - 1u));
                    if (pos < MAXD) g_ell_cv[base + pos] = make_int2(c, __float_as_int(v[j]));
                }
                cnt += __popc(mask);
            }
        }
        #pragma unroll
        for (int o = 16; o > 0; o >>= 1) wsum += __shfl_xor_sync(0xffffffffu, wsum, o);
        if (lane == 0) {
            g_row_len[warp]  = cnt < MAXD ? cnt : MAXD;
            g_row_wsum[warp] = wsum;
        }
    } else {
        // ---------- transpose + per-node BN partials ----------
        const int n   = blockIdx.x - 512;
        const int bt  = tid >> 3;
        const int f0  = (tid & 7) * 4;

        const float4 v = *(const float4*)(x + ((size_t)bt * N_NODES + n) * FEAT + f0);
        *(float4*)(g_xT + (size_t)n * (NBT * FEAT) + bt * FEAT + f0) = v;

        float s0 = v.x, s1 = v.y, s2 = v.z, s3 = v.w;
        float q0 = v.x * v.x, q1 = v.y * v.y, q2 = v.z * v.z, q3 = v.w * v.w;
        #pragma unroll
        for (int o = 8; o <= 16; o <<= 1) {
            s0 += __shfl_xor_sync(0xffffffffu, s0, o);
            s1 += __shfl_xor_sync(0xffffffffu, s1, o);
            s2 += __shfl_xor_sync(0xffffffffu, s2, o);
            s3 += __shfl_xor_sync(0xffffffffu, s3, o);
            q0 += __shfl_xor_sync(0xffffffffu, q0, o);
            q1 += __shfl_xor_sync(0xffffffffu, q1, o);
            q2 += __shfl_xor_sync(0xffffffffu, q2, o);
            q3 += __shfl_xor_sync(0xffffffffu, q3, o);
        }
        __shared__ float sh[8][64];
        if (lane < 8) {
            sh[w][f0 + 0]      = s0;  sh[w][f0 + 1]      = s1;
            sh[w][f0 + 2]      = s2;  sh[w][f0 + 3]      = s3;
            sh[w][32 + f0 + 0] = q0;  sh[w][32 + f0 + 1] = q1;
            sh[w][32 + f0 + 2] = q2;  sh[w][32 + f0 + 3] = q3;
        }
        __syncthreads();
        if (tid < 64) {
            float a = 0.f;
            #pragma unroll
            for (int i = 0; i < 8; ++i) a += sh[i][tid];
            g_partN[tid * N_NODES + n] = a;     // transposed layout
        }
    }
}

// ============================================================
// Kernel 2 (parallel finalize): blocks 0-63  -> stat column reduce
//                               blocks 64-87 -> Wcomb
//                               block  88    -> bcomb
// ============================================================
__global__ void __launch_bounds__(256)
finalize_kernel(const float* __restrict__ Wgcn,
                const float* __restrict__ bgcn,
                const float* __restrict__ Wih,
                const float* __restrict__ bih)
{
    const int tid = threadIdx.x;
    const int bid = blockIdx.x;

    if (bid < 64) {
        // deterministic fixed-order column reduction
        __shared__ float red[256];
        const float* p = g_partN + bid * N_NODES;
        float a = 0.f;
        #pragma unroll 4
        for (int i = tid; i < N_NODES; i += 256) a += p[i];
        red[tid] = a;
        __syncthreads();
        #pragma unroll
        for (int s = 128; s > 0; s >>= 1) {
            if (tid < s) red[tid] += red[tid + s];
            __syncthreads();
        }
        if (tid == 0) g_stat[bid] = red[0];
    } else if (bid < 88) {
        const int idx = (bid - 64) * 256 + tid;   // < 6144
        const int f = idx / G3, j = idx % G3;
        float acc = 0.f;
        #pragma unroll 8
        for (int c = 0; c < 32; ++c) acc += Wgcn[f * 32 + c] * Wih[c * G3 + j];
        g_Wcomb[idx] = acc;
    } else {
        if (tid < G3) {
            float acc = bih[tid];
            #pragma unroll 8
            for (int c = 0; c < 32; ++c) acc += bgcn[c] * Wih[c * G3 + tid];
            g_bcomb[tid] = acc;
        }
    }
}

// ============================================================
// Kernel 3: aggregation (one block = one node, all 32 bt)
// BN affine derived locally from raw stats.
// ============================================================
__global__ void __launch_bounds__(256)
agg_kernel(const float* __restrict__ gamma, const float* __restrict__ beta)
{
    const int m   = blockIdx.x;
    const int tid = threadIdx.x;
    const int f   = tid & 31;
    const int bt0 = tid >> 5;

    const int len = g_row_len[m];
    const float wsum = g_row_wsum[m];
    const int2* cv = g_ell_cv + m * MAXD;

    float a0 = 0.f, a1 = 0.f, a2 = 0.f, a3 = 0.f;
    const int off = bt0 * FEAT + f;

    int k = 0;
    for (; k + 3 < len; k += 4) {
        const int2 e0 = cv[k], e1 = cv[k + 1], e2 = cv[k + 2], e3 = cv[k + 3];
        const float w0 = __int_as_float(e0.y), w1 = __int_as_float(e1.y);
        const float w2 = __int_as_float(e2.y), w3 = __int_as_float(e3.y);
        const float* p0 = g_xT + (size_t)e0.x * (NBT * FEAT) + off;
        const float* p1 = g_xT + (size_t)e1.x * (NBT * FEAT) + off;
        const float* p2 = g_xT + (size_t)e2.x * (NBT * FEAT) + off;
        const float* p3 = g_xT + (size_t)e3.x * (NBT * FEAT) + off;
        const float v00 = p0[0], v01 = p0[256], v02 = p0[512], v03 = p0[768];
        const float v10 = p1[0], v11 = p1[256], v12 = p1[512], v13 = p1[768];
        const float v20 = p2[0], v21 = p2[256], v22 = p2[512], v23 = p2[768];
        const float v30 = p3[0], v31 = p3[256], v32 = p3[512], v33 = p3[768];
        a0 += w0 * v00; a1 += w0 * v01; a2 += w0 * v02; a3 += w0 * v03;
        a0 += w1 * v10; a1 += w1 * v11; a2 += w1 * v12; a3 += w1 * v13;
        a0 += w2 * v20; a1 += w2 * v21; a2 += w2 * v22; a3 += w2 * v23;
        a0 += w3 * v30; a1 += w3 * v31; a2 += w3 * v32; a3 += w3 * v33;
    }
    for (; k < len; ++k) {
        const int2 e = cv[k];
        const float w = __int_as_float(e.y);
        const float* p = g_xT + (size_t)e.x * (NBT * FEAT) + off;
        a0 += w * p[0]; a1 += w * p[256]; a2 += w * p[512]; a3 += w * p[768];
    }

    const float M    = (float)NROWS;
    const float mean = g_stat[f] / M;
    const float var  = g_stat[32 + f] / M - mean * mean;
    const float A    = gamma[f] * rsqrtf(var + 1e-5f);
    const float C    = (beta[f] - mean * A) * wsum;
    g_ya[((size_t)(bt0 +  0) * N_NODES + m) * FEAT + f] = A * a0 + C;
    g_ya[((size_t)(bt0 +  8) * N_NODES + m) * FEAT + f] = A * a1 + C;
    g_ya[((size_t)(bt0 + 16) * N_NODES + m) * FEAT + f] = A * a2 + C;
    g_ya[((size_t)(bt0 + 24) * N_NODES + m) * FEAT + f] = A * a3 + C;
}

// ============================================================
// Kernel 4: GRU scan via mma.sync m16n8k16 fp16 (3-term split).
// block = 64 nodes x 1 batch, 256 threads, 2 blocks/SM, grid 256.
// 2 syncs per timestep.
// ============================================================
#define GK16(C, ACCN)                                                            \
{                                                                                \
    const uint4 ah = *(const uint4*)&sAh[(((C) * 4 + mw) * 32 + lane) * 4];      \
    const uint4 al = *(const uint4*)&sAl[(((C) * 4 + mw) * 32 + lane) * 4];      \
    _Pragma("unroll")                                                            \
    for (int tt = 0; tt < 12; ++tt) {                                            \
        const uint4 bq = *(const uint4*)&sB[(((C) * 24 + Ht + tt) * 32 + lane) * 4]; \
        const uint2 bh = make_uint2(bq.x, bq.y);                                 \
        const uint2 bl = make_uint2(bq.z, bq.w);                                 \
        float* cp = (tt < 8) ? accRZ[tt] : ACCN[tt - 8];                         \
        mma16(cp, ah, bh);                                                       \
        mma16(cp, al, bh);                                                       \
        mma16(cp, ah, bl);                                                       \
    }                                                                            \
}

__global__ void __launch_bounds__(GT, 2)
gru_mma_kernel(const float* __restrict__ Whh,
               const float* __restrict__ bhh,
               const float* __restrict__ Wd,
               const float* __restrict__ bd,
               float* __restrict__ out)
{
    extern __shared__ float sm[];
    float* sB    = sm + O_B;
    float* sAh   = sm + O_AH;
    float* sAl   = sm + O_AL;
    float* sBias = sm + O_BIAS;
    float* sWd   = sm + O_WD;
    float* sHead = sm + O_HEAD;

    const int tid  = threadIdx.x;
    const int wid  = tid >> 5;
    const int lane = tid & 31;
    const int mw   = wid >> 1;          // m16 tile 0..3
    const int H    = wid & 1;           // hd half
    const int Ht   = H * 12;            // B tile base

    const int b   = blockIdx.x >> 6;
    const int gm0 = (blockIdx.x & 63) * NP;

    // ---- zero A fragment regions (h0 = 0) ----
    for (int i = tid; i < 3072; i += GT) { sAh[i] = 0.0f; sAl[i] = 0.0f; }

    // ---- stage B fragments (fp16 hi/lo, permuted cols) ----
    {
        __half* pB = (__half*)sB;
        for (int idx = tid; idx < 96 * G3; idx += GT) {
            const int k = idx / G3, n = idx % G3;
            const float w = (k < 32) ? g_Wcomb[k * G3 + n] : Whh[(k - 32) * G3 + n];
            const __half hh = __float2half_rn(w);
            const __half hl = __float2half_rn(w - __half2float(hh));
            const int g    = n >> 6;
            const int hd   = n & 63;
            const int Hh   = hd >> 5;
            const int hdl  = hd & 31;
            const int tile = Hh * 12 + g * 4 + (hdl >> 3);
            const int ccol = hdl & 7;
            const int chunk = k >> 4;
            const int rem   = k & 15;
            const int lt    = ccol * 4 + ((rem & 7) >> 1);
            const int regB  = (rem >= 8) ? 1 : 0;
            const int hb    = rem & 1;
            const int base  = ((chunk * 24 + tile) * 32 + lt) * 4;
            pB[(base + regB) * 2 + hb]     = hh;
            pB[(base + 2 + regB) * 2 + hb] = hl;
        }
    }
    if (tid < HDIM) {
        sBias[tid]       = g_bcomb[tid]       + bhh[tid];        // r
        sBias[64 + tid]  = g_bcomb[64 + tid]  + bhh[64 + tid];   // z
        sBias[128 + tid] = g_bcomb[128 + tid];                   // n_i
        sBias[192 + tid] = bhh[128 + tid];                       // n_h
        sWd[tid]         = Wd[tid];
    }
    const float bdv = bd[0];

    // ---- epilogue geometry ----
    const int gr = lane >> 2;
    const int c0 = (lane & 3) * 2;

    float hprev[4][4];
    #pragma unroll
    for (int t = 0; t < 4; ++t)
        #pragma unroll
        for (int s = 0; s < 4; ++s) hprev[t][s] = 0.0f;

    // ---- ya staging geometry ----
    const int nodeS = tid >> 2;           // 0..63
    const int fc    = tid & 3;            // feature chunk: f base = fc*8
    const int baseS = (((fc >> 1) * 4 + (nodeS >> 4)) * 32 + (nodeS & 7) * 4) * 4
                      + ((fc & 1) ? 2 : 0) + (((nodeS & 15) >= 8) ? 1 : 0);

    // ---- stage ya_0 ----
    {
        const float* p = g_ya + ((size_t)(b * TSTEPS) * N_NODES + gm0 + nodeS) * FEAT + fc * 8;
        const float4 q0 = *(const float4*)(p);
        const float4 q1 = *(const float4*)(p + 4);
        float v[8];
        *(float4*)(v) = q0; *(float4*)(v + 4) = q1;
        #pragma unroll
        for (int j = 0; j < 4; ++j) {
            const float a = v[2 * j], bb = v[2 * j + 1];
            const __half ha = __float2half_rn(a);
            const __half hb = __float2half_rn(bb);
            sAh[baseS + j * 4] = __uint_as_float(pack_f16x2(a, bb));
            sAl[baseS + j * 4] = __uint_as_float(pack_f16x2(a - __half2float(ha),
                                                            bb - __half2float(hb)));
        }
    }
    __syncthreads();

    float4 pf0, pf1;

    for (int t8 = 0; t8 < TSTEPS; ++t8) {
        // ---- accumulators ----
        float accRZ[8][4], accNi[4][4], accNh[4][4];
        #pragma unroll
        for (int t = 0; t < 8; ++t)
            #pragma unroll
            for (int s = 0; s < 4; ++s) accRZ[t][s] = 0.0f;
        #pragma unroll
        for (int t = 0; t < 4; ++t)
            #pragma unroll
            for (int s = 0; s < 4; ++s) { accNi[t][s] = 0.0f; accNh[t][s] = 0.0f; }

        GK16(0, accNi) GK16(1, accNi)
        GK16(2, accNh) GK16(3, accNh) GK16(4, accNh) GK16(5, accNh)

        // prefetch next ya during GEMM
        if (t8 + 1 < TSTEPS) {
            const float* p = g_ya + ((size_t)(b * TSTEPS + t8 + 1) * N_NODES + gm0 + nodeS) * FEAT + fc * 8;
            pf0 = *(const float4*)(p);
            pf1 = *(const float4*)(p + 4);
        }
        __syncthreads();   // all warps done reading A frags (ya_t + h_t)

        // ---- register epilogue: gates, h update, head, h-frag + ya_{t+1} staging ----
        float hp0 = 0.0f, hp1 = 0.0f;
        #pragma unroll
        for (int t = 0; t < 4; ++t) {
            float hv[4];
            #pragma unroll
            for (int s = 0; s < 4; ++s) {
                const int cc = c0 + (s & 1);
                const int hd = H * 32 + t * 8 + cc;
                const float r = sigm(accRZ[t][s]     + sBias[hd]);
                const float z = sigm(accRZ[t + 4][s] + sBias[64 + hd]);
                const float n = tanh_fast(accNi[t][s] + sBias[128 + hd]
                                          + r * (accNh[t][s] + sBias[192 + hd]));
                hv[s] = (1.0f - z) * n + z * hprev[t][s];
                hprev[t][s] = hv[s];
            }
            hp0 += hv[0] * sWd[H * 32 + t * 8 + c0] + hv[1] * sWd[H * 32 + t * 8 + c0 + 1];
            hp1 += hv[2] * sWd[H * 32 + t * 8 + c0] + hv[3] * sWd[H * 32 + t * 8 + c0 + 1];
            // write h back into A fragments at k = 32 + H*32 + t*8 + cc
            const int chunk = 2 + H * 2 + (t >> 1);
            const int reg2  = (t & 1) * 2;
            const int base  = ((chunk * 4 + mw) * 32 + lane) * 4;
            const __half h0 = __float2half_rn(hv[0]);
            const __half h1 = __float2half_rn(hv[1]);
            const __half h2 = __float2half_rn(hv[2]);
            const __half h3 = __float2half_rn(hv[3]);
            sAh[base + reg2]     = __uint_as_float(pack_f16x2(hv[0], hv[1]));
            sAh[base + reg2 + 1] = __uint_as_float(pack_f16x2(hv[2], hv[3]));
            sAl[base + reg2]     = __uint_as_float(pack_f16x2(hv[0] - __half2float(h0),
                                                              hv[1] - __half2float(h1)));
            sAl[base + reg2 + 1] = __uint_as_float(pack_f16x2(hv[2] - __half2float(h2),
                                                              hv[3] - __half2float(h3)));
        }
        // stage ya_{t+1} (region disjoint from h frags)
        if (t8 + 1 < TSTEPS) {
            float v[8];
            *(float4*)(v) = pf0; *(float4*)(v + 4) = pf1;
            #pragma unroll
            for (int j = 0; j < 4; ++j) {
                const float a = v[2 * j], bb = v[2 * j + 1];
                const __half ha = __float2half_rn(a);
                const __half hb = __float2half_rn(bb);
                sAh[baseS + j * 4] = __uint_as_float(pack_f16x2(a, bb));
                sAl[baseS + j * 4] = __uint_as_float(pack_f16x2(a - __half2float(ha),
                                                                bb - __half2float(hb)));
            }
        }
        // head reduce across the 4 lanes sharing gr
        hp0 += __shfl_xor_sync(0xffffffffu, hp0, 1);
        hp0 += __shfl_xor_sync(0xffffffffu, hp0, 2);
        hp1 += __shfl_xor_sync(0xffffffffu, hp1, 1);
        hp1 += __shfl_xor_sync(0xffffffffu, hp1, 2);
        if ((lane & 3) == 0) {
            sHead[H * 64 + mw * 16 + gr]     = hp0;
            sHead[H * 64 + mw * 16 + gr + 8] = hp1;
        }
        __syncthreads();   // h frags + ya frags + sHead complete

        if (tid < NP) {
            out[(size_t)(b * TSTEPS + t8) * N_NODES + gm0 + tid] =
                bdv + sHead[tid] + sHead[64 + tid];
        }
        // out STG overlaps the next iteration's GEMM (no barrier between).
    }
}

// ============================================================
// launch
// ============================================================
extern "C" void kernel_launch(void* const* d_in, const int* in_sizes, int n_in,
                              void* d_out, int out_size)
{
    const float* x     = (const float*)d_in[0];
    const float* adj   = (const float*)d_in[1];
    const float* gamma = (const float*)d_in[2];
    const float* beta  = (const float*)d_in[3];
    const float* Wgcn  = (const float*)d_in[4];
    const float* bgcn  = (const float*)d_in[5];
    const float* Wih   = (const float*)d_in[6];
    const float* Whh   = (const float*)d_in[7];
    const float* bih   = (const float*)d_in[8];
    const float* bhh   = (const float*)d_in[9];
    const float* Wd    = (const float*)d_in[10];
    const float* bd    = (const float*)d_in[11];
    float* out = (float*)d_out;

    const int smem_bytes = SM_FLOATS * (int)sizeof(float);   // 100096
    cudaFuncSetAttribute(gru_mma_kernel, cudaFuncAttributeMaxDynamicSharedMemorySize, smem_bytes);

    prep_kernel<<<512 + N_NODES, 256>>>(adj, x);
    finalize_kernel<<<89, 256>>>(Wgcn, bgcn, Wih, bih);
    agg_kernel<<<N_NODES, 256>>>(gamma, beta);
    gru_mma_kernel<<<BATCH * (N_NODES / NP), GT, smem_bytes>>>(Whh, bhh, Wd, bd, out);
}

// round 10
// speedup vs baseline: 1.5755x; 1.1119x over previous
#include <cuda_runtime.h>
#include <cuda_fp16.h>
#include <cstdint>

#define N_NODES 4096
#define FEAT    32
#define G3      192
#define HDIM    64
#define BATCH   4
#define TSTEPS  8
#define NBT     (BATCH*TSTEPS)           // 32
#define MAXD    128
#define NROWS   (NBT*N_NODES)            // 131072

// ---- gru mma kernel geometry ----
#define NP      64                        // nodes per block
#define GT      256                       // threads (8 warps = 2 m-groups x 4 col-groups)

// smem float offsets (gru)
#define O_B     0                         // B frags [6 k16][24 tiles][32 lanes][bh0 bh1 bl0 bl1]
#define O_AH    18432                     // A hi frags [6 k16][4 m16][32 lanes][4]
#define O_AL    21504                     // A lo frags
#define O_BIAS  24576                     // [256] r|z|ni|nh
#define O_WD    24832                     // [64]
#define O_HEAD  24896                     // [256] (q*64 + node)
#define SM_FLOATS 25152                   // 100608 bytes

// -------- static device scratch --------
__device__ int      g_row_len[N_NODES];
__device__ float    g_row_wsum[N_NODES];
__device__ int2     g_ell_cv[N_NODES * MAXD];
__device__ float    g_Wcomb[FEAT * G3];
__device__ float    g_bcomb[G3];
__device__ float    g_partN[64 * N_NODES];          // TRANSPOSED: [stat c][node n]
__device__ float    g_stat[64];                     // 0-31 sum, 32-63 sumsq
__device__ uint32_t g_xT2[(size_t)N_NODES * 16 * 32];  // [n][btp][f] half2=(bt, bt+16), 8MB
__device__ float    g_ya[(size_t)NROWS * FEAT];

// ============================================================
// helpers
// ============================================================
__device__ __forceinline__ float sigm(float v) { return __fdividef(1.0f, 1.0f + __expf(-v)); }
__device__ __forceinline__ float tanh_fast(float v) {
    const float e = __expf(-2.0f * v);
    return __fdividef(1.0f - e, 1.0f + e);
}
// pack two floats to f16x2 (first arg -> low half)
__device__ __forceinline__ uint32_t pack_f16x2(float lo_val, float hi_val) {
    uint32_t r;
    asm("cvt.rn.f16x2.f32 %0, %1, %2;" : "=r"(r) : "f"(hi_val), "f"(lo_val));
    return r;
}
__device__ __forceinline__ void mma16(float* d, const uint4& a, const uint2& b) {
    asm volatile(
        "mma.sync.aligned.m16n8k16.row.col.f32.f16.f16.f32 "
        "{%0,%1,%2,%3}, {%4,%5,%6,%7}, {%8,%9}, {%0,%1,%2,%3};"
        : "+f"(d[0]), "+f"(d[1]), "+f"(d[2]), "+f"(d[3])
        : "r"(a.x), "r"(a.y), "r"(a.z), "r"(a.w), "r"(b.x), "r"(b.y));
}

// ============================================================
// Kernel 1 (fused prep): blocks [0,512)   -> dense adj -> packed ELL
//                        blocks [512,4608)-> transpose x (fp16x2) + BN partials
// ============================================================
__global__ void __launch_bounds__(256)
prep_kernel(const float* __restrict__ adj, const float* __restrict__ x)
{
    const int tid  = threadIdx.x;
    const int lane = tid & 31;
    const int w    = tid >> 5;

    if (blockIdx.x < 512) {
        // ---------- ELL build: warp = one adjacency row, MLP=8 ----------
        const int warp = blockIdx.x * 8 + w;
        const float* row = adj + (size_t)warp * N_NODES;
        const int base = warp * MAXD;
        int cnt = 0; float wsum = 0.f;
        #pragma unroll 1
        for (int g = 0; g < N_NODES / 256; ++g) {
            float v[8];
            #pragma unroll
            for (int j = 0; j < 8; ++j) v[j] = row[g * 256 + j * 32 + lane];
            #pragma unroll
            for (int j = 0; j < 8; ++j) {
                const int c = g * 256 + j * 32 + lane;
                wsum += v[j];
                const unsigned mask = __ballot_sync(0xffffffffu, v[j] != 0.0f);
                if (v[j] != 0.0f) {
                    const int pos = cnt + __popc(mask & ((1u << lane) - 1u));
                    if (pos < MAXD) g_ell_cv[base + pos] = make_int2(c, __float_as_int(v[j]));
                }
                cnt += __popc(mask);
            }
        }
        #pragma unroll
        for (int o = 16; o > 0; o >>= 1) wsum += __shfl_xor_sync(0xffffffffu, wsum, o);
        if (lane == 0) {
            g_row_len[warp]  = cnt < MAXD ? cnt : MAXD;
            g_row_wsum[warp] = wsum;
        }
    } else {
        // ---------- transpose to fp16x2 + per-node BN partials ----------
        const int n   = blockIdx.x - 512;
        const int bt  = tid >> 3;
        const int f0  = (tid & 7) * 4;

        __shared__ float sh[8][64];
        __shared__ float xbuf[32][32];

        const float4 v = *(const float4*)(x + ((size_t)bt * N_NODES + n) * FEAT + f0);
        *(float4*)&xbuf[bt][f0] = v;

        float s0 = v.x, s1 = v.y, s2 = v.z, s3 = v.w;
        float q0 = v.x * v.x, q1 = v.y * v.y, q2 = v.z * v.z, q3 = v.w * v.w;
        #pragma unroll
        for (int o = 8; o <= 16; o <<= 1) {
            s0 += __shfl_xor_sync(0xffffffffu, s0, o);
            s1 += __shfl_xor_sync(0xffffffffu, s1, o);
            s2 += __shfl_xor_sync(0xffffffffu, s2, o);
            s3 += __shfl_xor_sync(0xffffffffu, s3, o);
            q0 += __shfl_xor_sync(0xffffffffu, q0, o);
            q1 += __shfl_xor_sync(0xffffffffu, q1, o);
            q2 += __shfl_xor_sync(0xffffffffu, q2, o);
            q3 += __shfl_xor_sync(0xffffffffu, q3, o);
        }
        if (lane < 8) {
            sh[w][f0 + 0]      = s0;  sh[w][f0 + 1]      = s1;
            sh[w][f0 + 2]      = s2;  sh[w][f0 + 3]      = s3;
            sh[w][32 + f0 + 0] = q0;  sh[w][32 + f0 + 1] = q1;
            sh[w][32 + f0 + 2] = q2;  sh[w][32 + f0 + 3] = q3;
        }
        __syncthreads();
        if (tid < 64) {
            float a = 0.f;
            #pragma unroll
            for (int i = 0; i < 8; ++i) a += sh[i][tid];
            g_partN[tid * N_NODES + n] = a;     // transposed layout
        }
        if (tid < 128) {
            const int btp = tid >> 3;
            const int fq  = (tid & 7) * 4;
            const float4 a = *(const float4*)&xbuf[btp][fq];
            const float4 b = *(const float4*)&xbuf[btp + 16][fq];
            uint4 wv;
            wv.x = pack_f16x2(a.x, b.x);
            wv.y = pack_f16x2(a.y, b.y);
            wv.z = pack_f16x2(a.z, b.z);
            wv.w = pack_f16x2(a.w, b.w);
            *(uint4*)&g_xT2[((size_t)n * 16 + btp) * 32 + fq] = wv;
        }
    }
}

// ============================================================
// Kernel 2 (parallel finalize): blocks 0-63  -> stat column reduce
//                               blocks 64-87 -> Wcomb, block 88 -> bcomb
// ============================================================
__global__ void __launch_bounds__(256)
finalize_kernel(const float* __restrict__ Wgcn,
                const float* __restrict__ bgcn,
                const float* __restrict__ Wih,
                const float* __restrict__ bih)
{
    const int tid = threadIdx.x;
    const int bid = blockIdx.x;

    if (bid < 64) {
        __shared__ float red[256];
        const float* p = g_partN + bid * N_NODES;
        float a = 0.f;
        #pragma unroll 4
        for (int i = tid; i < N_NODES; i += 256) a += p[i];
        red[tid] = a;
        __syncthreads();
        #pragma unroll
        for (int s = 128; s > 0; s >>= 1) {
            if (tid < s) red[tid] += red[tid + s];
            __syncthreads();
        }
        if (tid == 0) g_stat[bid] = red[0];
    } else if (bid < 88) {
        const int idx = (bid - 64) * 256 + tid;   // < 6144
        const int f = idx / G3, j = idx % G3;
        float acc = 0.f;
        #pragma unroll 8
        for (int c = 0; c < 32; ++c) acc += Wgcn[f * 32 + c] * Wih[c * G3 + j];
        g_Wcomb[idx] = acc;
    } else {
        if (tid < G3) {
            float acc = bih[tid];
            #pragma unroll 8
            for (int c = 0; c < 32; ++c) acc += bgcn[c] * Wih[c * G3 + tid];
            g_bcomb[tid] = acc;
        }
    }
}

// ============================================================
// Kernel 3: aggregation (one block = one node, all 32 bt), fp16 x
// thread (f=lane, bt0=tid>>5): 2 half2 loads per neighbor
// ============================================================
__global__ void __launch_bounds__(256)
agg_kernel(const float* __restrict__ gamma, const float* __restrict__ beta)
{
    const int m   = blockIdx.x;
    const int tid = threadIdx.x;
    const int f   = tid & 31;
    const int bt0 = tid >> 5;

    const int len = g_row_len[m];
    const float wsum = g_row_wsum[m];
    const int2* cv = g_ell_cv + m * MAXD;

    float a0 = 0.f, a1 = 0.f, a2 = 0.f, a3 = 0.f;
    const int off = bt0 * 32 + f;

    int k = 0;
    for (; k + 3 < len; k += 4) {
        const int2 e0 = cv[k], e1 = cv[k + 1], e2 = cv[k + 2], e3 = cv[k + 3];
        const float w0 = __int_as_float(e0.y), w1 = __int_as_float(e1.y);
        const float w2 = __int_as_float(e2.y), w3 = __int_as_float(e3.y);
        const uint32_t* p0 = g_xT2 + (size_t)e0.x * 512 + off;
        const uint32_t* p1 = g_xT2 + (size_t)e1.x * 512 + off;
        const uint32_t* p2 = g_xT2 + (size_t)e2.x * 512 + off;
        const uint32_t* p3 = g_xT2 + (size_t)e3.x * 512 + off;
        const uint32_t r00 = p0[0], r01 = p0[256];
        const uint32_t r10 = p1[0], r11 = p1[256];
        const uint32_t r20 = p2[0], r21 = p2[256];
        const uint32_t r30 = p3[0], r31 = p3[256];
        {
            const float2 u0 = __half22float2(*(const __half2*)&r00);
            const float2 u1 = __half22float2(*(const __half2*)&r01);
            a0 += w0 * u0.x; a2 += w0 * u0.y; a1 += w0 * u1.x; a3 += w0 * u1.y;
        }
        {
            const float2 u0 = __half22float2(*(const __half2*)&r10);
            const float2 u1 = __half22float2(*(const __half2*)&r11);
            a0 += w1 * u0.x; a2 += w1 * u0.y; a1 += w1 * u1.x; a3 += w1 * u1.y;
        }
        {
            const float2 u0 = __half22float2(*(const __half2*)&r20);
            const float2 u1 = __half22float2(*(const __half2*)&r21);
            a0 += w2 * u0.x; a2 += w2 * u0.y; a1 += w2 * u1.x; a3 += w2 * u1.y;
        }
        {
            const float2 u0 = __half22float2(*(const __half2*)&r30);
            const float2 u1 = __half22float2(*(const __half2*)&r31);
            a0 += w3 * u0.x; a2 += w3 * u0.y; a1 += w3 * u1.x; a3 += w3 * u1.y;
        }
    }
    for (; k < len; ++k) {
        const int2 e = cv[k];
        const float w = __int_as_float(e.y);
        const uint32_t* p = g_xT2 + (size_t)e.x * 512 + off;
        const float2 u0 = __half22float2(*(const __half2*)&p[0]);
        const float2 u1 = __half22float2(*(const __half2*)&p[256]);
        a0 += w * u0.x; a2 += w * u0.y; a1 += w * u1.x; a3 += w * u1.y;
    }

    const float M    = (float)NROWS;
    const float mean = g_stat[f] / M;
    const float var  = g_stat[32 + f] / M - mean * mean;
    const float A    = gamma[f] * rsqrtf(var + 1e-5f);
    const float C    = (beta[f] - mean * A) * wsum;
    g_ya[((size_t)(bt0 +  0) * N_NODES + m) * FEAT + f] = A * a0 + C;
    g_ya[((size_t)(bt0 +  8) * N_NODES + m) * FEAT + f] = A * a1 + C;
    g_ya[((size_t)(bt0 + 16) * N_NODES + m) * FEAT + f] = A * a2 + C;
    g_ya[((size_t)(bt0 + 24) * N_NODES + m) * FEAT + f] = A * a3 + C;
}

// ============================================================
// Kernel 4: GRU scan via mma.sync m16n8k16 fp16 (3-term split).
// block = 64 nodes x 1 batch, 256 threads, 2 blocks/SM, grid 256.
// warp = (m-group mq: 2 m16 tiles) x (col-group q: 16 hd cols).
// Warp tiles tt=0..5: 0-1 r(sub), 2-3 z(sub), 4-5 n(sub).
// B tile index = q*6 + g*2 + sub. 60 LDS128 per warp per t.
// ============================================================
#define GK16(C, ACCN)                                                             \
{                                                                                 \
    const uint4 ah0 = *(const uint4*)&sAh[(((C) * 4 + mq * 2    ) * 32 + lane) * 4]; \
    const uint4 al0 = *(const uint4*)&sAl[(((C) * 4 + mq * 2    ) * 32 + lane) * 4]; \
    const uint4 ah1 = *(const uint4*)&sAh[(((C) * 4 + mq * 2 + 1) * 32 + lane) * 4]; \
    const uint4 al1 = *(const uint4*)&sAl[(((C) * 4 + mq * 2 + 1) * 32 + lane) * 4]; \
    _Pragma("unroll")                                                             \
    for (int tt = 0; tt < 6; ++tt) {                                              \
        const uint4 bq = *(const uint4*)&sB[(((C) * 24 + tbase + tt) * 32 + lane) * 4]; \
        const uint2 bh = make_uint2(bq.x, bq.y);                                  \
        const uint2 bl = make_uint2(bq.z, bq.w);                                  \
        float* c0p; float* c1p;                                                   \
        if (tt < 4) { c0p = accRZ[0][tt];     c1p = accRZ[1][tt];     }           \
        else        { c0p = ACCN[0][tt - 4];  c1p = ACCN[1][tt - 4];  }           \
        mma16(c0p, ah0, bh); mma16(c0p, al0, bh); mma16(c0p, ah0, bl);            \
        mma16(c1p, ah1, bh); mma16(c1p, al1, bh); mma16(c1p, ah1, bl);            \
    }                                                                             \
}

__global__ void __launch_bounds__(GT, 2)
gru_mma_kernel(const float* __restrict__ Whh,
               const float* __restrict__ bhh,
               const float* __restrict__ Wd,
               const float* __restrict__ bd,
               float* __restrict__ out)
{
    extern __shared__ float sm[];
    float* sB    = sm + O_B;
    float* sAh   = sm + O_AH;
    float* sAl   = sm + O_AL;
    float* sBias = sm + O_BIAS;
    float* sWd   = sm + O_WD;
    float* sHead = sm + O_HEAD;

    const int tid  = threadIdx.x;
    const int wid  = tid >> 5;
    const int lane = tid & 31;
    const int mq   = wid >> 2;          // m-group 0..1 (m16 tiles mq*2, mq*2+1)
    const int q    = wid & 3;           // col-group 0..3 (hd in [q*16, q*16+16))
    const int tbase = q * 6;

    const int b   = blockIdx.x >> 6;
    const int gm0 = (blockIdx.x & 63) * NP;

    // ---- zero A fragment regions (h0 = 0) ----
    for (int i = tid; i < 3072; i += GT) { sAh[i] = 0.0f; sAl[i] = 0.0f; }

    // ---- stage B fragments (fp16 hi/lo, q-major tile order) ----
    {
        __half* pB = (__half*)sB;
        for (int idx = tid; idx < 96 * G3; idx += GT) {
            const int k = idx / G3, n = idx % G3;
            const float w = (k < 32) ? g_Wcomb[k * G3 + n] : Whh[(k - 32) * G3 + n];
            const __half hh = __float2half_rn(w);
            const __half hl = __float2half_rn(w - __half2float(hh));
            const int g    = n >> 6;
            const int hd   = n & 63;
            const int j    = hd >> 3;
            const int qq   = j >> 1;
            const int sub  = j & 1;
            const int tile = qq * 6 + g * 2 + sub;
            const int ccol = hd & 7;
            const int chunk = k >> 4;
            const int rem   = k & 15;
            const int lt    = ccol * 4 + ((rem & 7) >> 1);
            const int regB  = (rem >= 8) ? 1 : 0;
            const int hb    = rem & 1;
            const int base  = ((chunk * 24 + tile) * 32 + lt) * 4;
            pB[(base + regB) * 2 + hb]     = hh;
            pB[(base + 2 + regB) * 2 + hb] = hl;
        }
    }
    if (tid < HDIM) {
        sBias[tid]       = g_bcomb[tid]       + bhh[tid];        // r
        sBias[64 + tid]  = g_bcomb[64 + tid]  + bhh[64 + tid];   // z
        sBias[128 + tid] = g_bcomb[128 + tid];                   // n_i
        sBias[192 + tid] = bhh[128 + tid];                       // n_h
        sWd[tid]         = Wd[tid];
    }
    const float bdv = bd[0];

    // ---- epilogue geometry ----
    const int gr = lane >> 2;
    const int c0 = (lane & 3) * 2;

    float hprev[2][2][4];
    #pragma unroll
    for (int m = 0; m < 2; ++m)
        #pragma unroll
        for (int sub = 0; sub < 2; ++sub)
            #pragma unroll
            for (int s = 0; s < 4; ++s) hprev[m][sub][s] = 0.0f;

    // ---- ya staging geometry ----
    const int nodeS = tid >> 2;           // 0..63
    const int fc    = tid & 3;            // feature chunk: f base = fc*8
    const int baseS = (((fc >> 1) * 4 + (nodeS >> 4)) * 32 + (nodeS & 7) * 4) * 4
                      + ((fc & 1) ? 2 : 0) + (((nodeS & 15) >= 8) ? 1 : 0);

    // ---- stage ya_0 ----
    {
        const float* p = g_ya + ((size_t)(b * TSTEPS) * N_NODES + gm0 + nodeS) * FEAT + fc * 8;
        const float4 q0 = *(const float4*)(p);
        const float4 q1 = *(const float4*)(p + 4);
        float v[8];
        *(float4*)(v) = q0; *(float4*)(v + 4) = q1;
        #pragma unroll
        for (int j = 0; j < 4; ++j) {
            const float a = v[2 * j], bb = v[2 * j + 1];
            const __half ha = __float2half_rn(a);
            const __half hb = __float2half_rn(bb);
            sAh[baseS + j * 4] = __uint_as_float(pack_f16x2(a, bb));
            sAl[baseS + j * 4] = __uint_as_float(pack_f16x2(a - __half2float(ha),
                                                            bb - __half2float(hb)));
        }
    }
    __syncthreads();

    float4 pf0, pf1;

    for (int t8 = 0; t8 < TSTEPS; ++t8) {
        // ---- accumulators ----
        float accRZ[2][4][4], accNi[2][2][4], accNh[2][2][4];
        #pragma unroll
        for (int m = 0; m < 2; ++m) {
            #pragma unroll
            for (int t = 0; t < 4; ++t)
                #pragma unroll
                for (int s = 0; s < 4; ++s) accRZ[m][t][s] = 0.0f;
            #pragma unroll
            for (int t = 0; t < 2; ++t)
                #pragma unroll
                for (int s = 0; s < 4; ++s) { accNi[m][t][s] = 0.0f; accNh[m][t][s] = 0.0f; }
        }

        GK16(0, accNi) GK16(1, accNi)
        GK16(2, accNh) GK16(3, accNh) GK16(4, accNh) GK16(5, accNh)

        // prefetch next ya during GEMM
        if (t8 + 1 < TSTEPS) {
            const float* p = g_ya + ((size_t)(b * TSTEPS + t8 + 1) * N_NODES + gm0 + nodeS) * FEAT + fc * 8;
            pf0 = *(const float4*)(p);
            pf1 = *(const float4*)(p + 4);
        }
        __syncthreads();   // all warps done reading A frags (ya_t + h_t)

        // ---- register epilogue ----
        float hp[2][2] = {{0.f, 0.f}, {0.f, 0.f}};
        #pragma unroll
        for (int m = 0; m < 2; ++m) {
            #pragma unroll
            for (int sub = 0; sub < 2; ++sub) {
                float hv[4];
                #pragma unroll
                for (int s = 0; s < 4; ++s) {
                    const int hd = q * 16 + sub * 8 + c0 + (s & 1);
                    const float r = sigm(accRZ[m][sub][s]     + sBias[hd]);
                    const float z = sigm(accRZ[m][2 + sub][s] + sBias[64 + hd]);
                    const float n = tanh_fast(accNi[m][sub][s] + sBias[128 + hd]
                                              + r * (accNh[m][sub][s] + sBias[192 + hd]));
                    hv[s] = (1.0f - z) * n + z * hprev[m][sub][s];
                    hprev[m][sub][s] = hv[s];
                    hp[m][s >> 1] += hv[s] * sWd[hd];
                }
                // write h into A frags: chunk = 2+q, reg = sub*2 + rowhalf, lane'=lane
                const int base = (((2 + q) * 4 + mq * 2 + m) * 32 + lane) * 4;
                const __half h0 = __float2half_rn(hv[0]);
                const __half h1 = __float2half_rn(hv[1]);
                const __half h2 = __float2half_rn(hv[2]);
                const __half h3 = __float2half_rn(hv[3]);
                sAh[base + sub * 2]     = __uint_as_float(pack_f16x2(hv[0], hv[1]));
                sAh[base + sub * 2 + 1] = __uint_as_float(pack_f16x2(hv[2], hv[3]));
                sAl[base + sub * 2]     = __uint_as_float(pack_f16x2(hv[0] - __half2float(h0),
                                                                     hv[1] - __half2float(h1)));
                sAl[base + sub * 2 + 1] = __uint_as_float(pack_f16x2(hv[2] - __half2float(h2),
                                                                     hv[3] - __half2float(h3)));
            }
        }
        // stage ya_{t+1} (chunks 0-1, disjoint from h chunks 2-5)
        if (t8 + 1 < TSTEPS) {
            float v[8];
            *(float4*)(v) = pf0; *(float4*)(v + 4) = pf1;
            #pragma unroll
            for (int j = 0; j < 4; ++j) {
                const float a = v[2 * j], bb = v[2 * j + 1];
                const __half ha = __float2half_rn(a);
                const __half hb = __float2half_rn(bb);
                sAh[baseS + j * 4] = __uint_as_float(pack_f16x2(a, bb));
                sAl[baseS + j * 4] = __uint_as_float(pack_f16x2(a - __half2float(ha),
                                                                bb - __half2float(hb)));
            }
        }
        // head reduce across the 4 lanes sharing gr
        #pragma unroll
        for (int m = 0; m < 2; ++m) {
            hp[m][0] += __shfl_xor_sync(0xffffffffu, hp[m][0], 1);
            hp[m][0] += __shfl_xor_sync(0xffffffffu, hp[m][0], 2);
            hp[m][1] += __shfl_xor_sync(0xffffffffu, hp[m][1], 1);
            hp[m][1] += __shfl_xor_sync(0xffffffffu, hp[m][1], 2);
        }
        if ((lane & 3) == 0) {
            #pragma unroll
            for (int m = 0; m < 2; ++m) {
                const int node = (mq * 2 + m) * 16 + gr;
                sHead[q * 64 + node]     = hp[m][0];
                sHead[q * 64 + node + 8] = hp[m][1];
            }
        }
        __syncthreads();   // h frags + ya frags + sHead complete

        if (tid < NP) {
            out[(size_t)(b * TSTEPS + t8) * N_NODES + gm0 + tid] =
                bdv + sHead[tid] + sHead[64 + tid] + sHead[128 + tid] + sHead[192 + tid];
        }
        // out STG overlaps the next iteration's GEMM (no barrier between).
    }
}

// ============================================================
// launch
// ============================================================
extern "C" void kernel_launch(void* const* d_in, const int* in_sizes, int n_in,
                              void* d_out, int out_size)
{
    const float* x     = (const float*)d_in[0];
    const float* adj   = (const float*)d_in[1];
    const float* gamma = (const float*)d_in[2];
    const float* beta  = (const float*)d_in[3];
    const float* Wgcn  = (const float*)d_in[4];
    const float* bgcn  = (const float*)d_in[5];
    const float* Wih   = (const float*)d_in[6];
    const float* Whh   = (const float*)d_in[7];
    const float* bih   = (const float*)d_in[8];
    const float* bhh   = (const float*)d_in[9];
    const float* Wd    = (const float*)d_in[10];
    const float* bd    = (const float*)d_in[11];
    float* out = (float*)d_out;

    const int smem_bytes = SM_FLOATS * (int)sizeof(float);   // 100608
    cudaFuncSetAttribute(gru_mma_kernel, cudaFuncAttributeMaxDynamicSharedMemorySize, smem_bytes);

    prep_kernel<<<512 + N_NODES, 256>>>(adj, x);
    finalize_kernel<<<89, 256>>>(Wgcn, bgcn, Wih, bih);
    agg_kernel<<<N_NODES, 256>>>(gamma, beta);
    gru_mma_kernel<<<BATCH * (N_NODES / NP), GT, smem_bytes>>>(Whh, bhh, Wd, bd, out);
}